// round 14
// baseline (speedup 1.0000x reference)
#include <cuda_runtime.h>
#include <math.h>
#include <stdint.h>

#define U     256
#define SZ    65536          // U*U
#define BATCH 32768
#define NL    6
#define DIN   784
#define DOUT  10
#define NB    32             // panel width
#define NSTEP (U / NB)       // 8 block steps
#define NCTA  148            // one CTA per SM -> co-resident
#define NT    512            // threads per CTA

// ===================== device-global scratch (no runtime allocs) =====================
__device__ float g_M   [NL][SZ];          // GENP inverse; later reused as tree bufs
__device__ float g_M2  [NL][SZ];          // Newton-refined inverse
__device__ float g_R   [NL][SZ];          // Newton residual
__device__ float g_MTn [NL][SZ];          // -(M2)^T
__device__ float g_Mul8[NSTEP][NL][NB * U]; // multipliers, per-step buffers, [p][r]
__device__ float g_ipiv[NL][U];           // 1/pivot per global step
__device__ unsigned int g_flagw[NL][NSTEP];
__device__ float g_c   [U];               // final constant c0
__device__ float g_G   [DOUT * U];
__device__ float g_F   [DIN * DOUT];
__device__ float g_f   [16];
__device__ unsigned int g_barcnt = 0;     // grid barrier state
__device__ unsigned int g_bargen = 0;

// =====================================================================
// device-wide barrier (proven round-13 pattern)
// =====================================================================
__device__ __forceinline__ void grid_sync() {
    __syncthreads();
    if (threadIdx.x == 0) {
        __threadfence();
        const unsigned int gen = atomicAdd(&g_bargen, 0u);
        if (atomicAdd(&g_barcnt, 1u) == NCTA - 1) {
            g_barcnt = 0;
            __threadfence();
            atomicAdd(&g_bargen, 1u);
        } else {
            while (atomicAdd(&g_bargen, 0u) == gen) { }
        }
    }
    __syncthreads();
}

// =====================================================================
// inversion body: 2 threads per row (h = tid&1, r = tid>>1).
// Per-element arithmetic sequence identical to round-12; cross-half
// scalars travel by warp-uniform shfl between lane-adjacent halves.
// =====================================================================
__device__ void invert_body(const float* __restrict__ B0, int l, int jt,
                            float (*sp)[NB], float* sipv) {
    const int tid  = threadIdx.x;
    const int r    = tid >> 1;          // row 0..255
    const int h    = tid & 1;           // column half
    const int lane = tid & 31;
    const int pbase = lane & ~1;        // pair base lane
    const float* A = B0 + (size_t)l * SZ;
    const int j0 = jt * NB;
    const int cb = h * 16;

    float t[16];
    #pragma unroll
    for (int c = 0; c < 16; c += 4)
        *(float4*)&t[c] = *(const float4*)&A[r * U + j0 + cb + c];

    #pragma unroll 1
    for (int kb = 0; kb < NSTEP; kb++) {
        float* Mul = &g_Mul8[kb][l][0];
        const int c0g = kb * NB;
        if (jt == kb) {
            // ---- pre-loop pivot prep (step 0; pivot col local 0 of half 0) ----
            {
                const float v0 = __shfl_sync(0xFFFFFFFFu, t[0], pbase);
                if (r == c0g) {
                    if (h == 0) { Mul[0 * U + r] = v0; g_ipiv[l][c0g] = 1.0f / v0; }
                    const float ip = 1.0f / v0;
                    #pragma unroll
                    for (int c = 0; c < 16; c++) t[c] *= ip;
                    if (h == 0) t[0] = ip;
                    #pragma unroll
                    for (int c = 0; c < 16; c++) sp[0][cb + c] = t[c];
                }
            }
            #pragma unroll
            for (int p = 0; p < NB; p++) {
                __syncthreads();
                const int gp = c0g + p;
                const int ob = p >> 4, lp = p & 15;
                const float f = __shfl_sync(0xFFFFFFFFu, t[lp], pbase | ob);
                if (r != gp) {
                    if (h == 0) Mul[p * U + r] = f;
                    const float ipv = sp[p & 1][p];
                    #pragma unroll
                    for (int c = 0; c < 16; c += 4) {
                        float4 s4 = *(const float4*)&sp[p & 1][cb + c];
                        t[c + 0] -= f * s4.x; t[c + 1] -= f * s4.y;
                        t[c + 2] -= f * s4.z; t[c + 3] -= f * s4.w;
                    }
                    if (h == ob) t[lp] = -f * ipv;
                }
                if (p + 1 < NB) {   // pipelined prep of next pivot row
                    const int ob2 = (p + 1) >> 4, lp2 = (p + 1) & 15;
                    const float vn = __shfl_sync(0xFFFFFFFFu, t[lp2], pbase | ob2);
                    if (r == gp + 1) {
                        if (h == 0) { Mul[(p + 1) * U + r] = vn; g_ipiv[l][gp + 1] = 1.0f / vn; }
                        const float ip2 = 1.0f / vn;
                        #pragma unroll
                        for (int c = 0; c < 16; c++) t[c] *= ip2;
                        if (h == ob2) t[lp2] = ip2;
                        #pragma unroll
                        for (int c = 0; c < 16; c++) sp[(p + 1) & 1][cb + c] = t[c];
                    }
                }
            }
            __threadfence();
            __syncthreads();
            if (tid == 0) atomicExch(&g_flagw[l][kb], 1u);
        } else {
            if (tid == 0) {
                while (atomicAdd(&g_flagw[l][kb], 0u) == 0u) { }
            }
            __syncthreads();
            float m[NB];
            #pragma unroll
            for (int p = 0; p < NB; p++) m[p] = Mul[p * U + r];
            if (tid < NB) sipv[tid] = g_ipiv[l][c0g + tid];
            __syncthreads();
            if (r == c0g) {
                const float ip = sipv[0];
                #pragma unroll
                for (int c = 0; c < 16; c++) { t[c] *= ip; sp[0][cb + c] = t[c]; }
            }
            #pragma unroll
            for (int p = 0; p < NB; p++) {
                __syncthreads();
                const int gp = c0g + p;
                if (r != gp) {
                    const float f = m[p];
                    #pragma unroll
                    for (int c = 0; c < 16; c += 4) {
                        float4 s4 = *(const float4*)&sp[p & 1][cb + c];
                        t[c + 0] -= f * s4.x; t[c + 1] -= f * s4.y;
                        t[c + 2] -= f * s4.z; t[c + 3] -= f * s4.w;
                    }
                    if (p + 1 < NB && r == gp + 1) {
                        const float ip2 = sipv[p + 1];
                        #pragma unroll
                        for (int c = 0; c < 16; c++) { t[c] *= ip2; sp[(p + 1) & 1][cb + c] = t[c]; }
                    }
                }
            }
        }
    }

    #pragma unroll
    for (int c = 0; c < 16; c += 4)
        *(float4*)&g_M[l][r * U + j0 + cb + c] = *(float4*)&t[c];
}

// =====================================================================
// 64x64x256 GEMM tile, 512 threads (2x4 fragment / thread).
// Per-output-element k accumulation order identical to round 13.
//   mode 0: C = A*B   mode 1: C = 2I - A*B
//   mode 2: C = A*B, plus transposed-negated store to T
// =====================================================================
__device__ void gemm_tile(float* shbuf,
                          const float* __restrict__ A, const float* __restrict__ Bm,
                          float* __restrict__ C, float* __restrict__ T,
                          int mode, int bx, int by) {
    float (*As)[68] = (float(*)[68])shbuf;
    float (*Bs)[68] = (float(*)[68])(shbuf + 32 * 68);
    const int tid = threadIdx.x;
    const int i0 = by * 64, j0 = bx * 64;
    const int rf = (tid >> 4) * 2, cf = (tid & 15) * 4;
    float acc[2][4];
    #pragma unroll
    for (int rr = 0; rr < 2; rr++)
        #pragma unroll
        for (int c = 0; c < 4; c++) acc[rr][c] = 0.0f;

    for (int k0 = 0; k0 < U; k0 += 32) {
        {
            const int ii = tid >> 3, kc = (tid & 7) * 4;
            float4 a = *(const float4*)&A[(i0 + ii) * U + k0 + kc];
            As[kc + 0][ii] = a.x; As[kc + 1][ii] = a.y;
            As[kc + 2][ii] = a.z; As[kc + 3][ii] = a.w;
            const int kk = tid >> 4, jc = (tid & 15) * 4;
            *(float4*)&Bs[kk][jc] = *(const float4*)&Bm[(k0 + kk) * U + j0 + jc];
        }
        __syncthreads();
        #pragma unroll
        for (int kk = 0; kk < 32; kk++) {
            float2 a2 = *(const float2*)&As[kk][rf];
            float4 b4 = *(const float4*)&Bs[kk][cf];
            acc[0][0] += a2.x * b4.x; acc[0][1] += a2.x * b4.y;
            acc[0][2] += a2.x * b4.z; acc[0][3] += a2.x * b4.w;
            acc[1][0] += a2.y * b4.x; acc[1][1] += a2.y * b4.y;
            acc[1][2] += a2.y * b4.z; acc[1][3] += a2.y * b4.w;
        }
        __syncthreads();
    }
    if (mode == 2) {
        #pragma unroll
        for (int rr = 0; rr < 2; rr++) {
            const int i = i0 + rf + rr;
            *(float4*)&C[i * U + j0 + cf] =
                make_float4(acc[rr][0], acc[rr][1], acc[rr][2], acc[rr][3]);
        }
        #pragma unroll
        for (int c = 0; c < 4; c++) {
            const int j = j0 + cf + c;
            *(float2*)&T[j * U + i0 + rf] = make_float2(-acc[0][c], -acc[1][c]);
        }
    } else {
        #pragma unroll
        for (int rr = 0; rr < 2; rr++) {
            const int i = i0 + rf + rr;
            #pragma unroll
            for (int c = 0; c < 4; c++) {
                const int j = j0 + cf + c;
                float v = acc[rr][c];
                if (mode == 1) v = ((i == j) ? 2.0f : 0.0f) - v;
                C[i * U + j] = v;
            }
        }
    }
}

// =====================================================================
// constant-chain layers [l0,l1): c0' = MTn_l*c1 ; c1' = M2_l*(c0+q_l)
// =====================================================================
__device__ void const_layers(int l0, int l1, const float* __restrict__ q,
                             float* c0s, float* c1s, float* rq) {
    const int tid = threadIdx.x;
    const int half = tid >> 8, n = tid & 255;
    for (int l = l0; l < l1; l++) {
        __syncthreads();
        if (tid < U) rq[tid] = c0s[tid] + q[l * U + tid];
        __syncthreads();
        const float* A = half ? &g_M2[l][0] : &g_MTn[l][0];
        const float* v = half ? rq : c1s;
        float acc = 0.0f;
        for (int m = 0; m < U; m += 4) {
            float4 a4 = *(const float4*)&A[n * U + m];
            acc += a4.x * v[m];     acc += a4.y * v[m + 1];
            acc += a4.z * v[m + 2]; acc += a4.w * v[m + 3];
        }
        __syncthreads();
        if (half) c1s[n] = acc; else c0s[n] = acc;
    }
}

// =====================================================================
// foldG (512 threads, compute guarded to 256)
// =====================================================================
__device__ void foldG_body(float* shbuf, const float* __restrict__ Wout,
                           const float* __restrict__ K, const float* __restrict__ c0,
                           const float* __restrict__ bin, const float* __restrict__ bout) {
    float* Ws = shbuf;
    float* Gs = shbuf + U * DOUT;
    const int tid = threadIdx.x;
    for (int e = tid; e < U * DOUT; e += NT) Ws[e] = Wout[e];
    __syncthreads();
    if (tid < 256) {
        const int m = tid;
        float acc[DOUT];
        #pragma unroll
        for (int d = 0; d < DOUT; d++) acc[d] = 0.0f;
        for (int n = 0; n < U; n++) {
            const float xv = K[n * U + m];
            #pragma unroll
            for (int d = 0; d < DOUT; d++) acc[d] += Ws[n * DOUT + d] * xv;
        }
        #pragma unroll
        for (int d = 0; d < DOUT; d++) { g_G[d * U + m] = acc[d]; Gs[d * U + m] = acc[d]; }
    }
    __syncthreads();
    if (tid < DOUT) {
        float f = bout[tid];
        for (int e = 0; e < U; e++) f += Gs[tid * U + e] * bin[e];
        for (int n = 0; n < U; n++) f += Ws[n * DOUT + tid] * c0[n];
        g_f[tid] = f;
    }
}

// =====================================================================
// foldF: F[k][d] = sum_m G[d][m]*Win[k][m]  (k-blocks of 512)
// =====================================================================
__device__ void foldF_body(float* shbuf, const float* __restrict__ Win, int blk) {
    float* Gs = shbuf;
    const int tid = threadIdx.x;
    for (int e = tid; e < DOUT * U; e += NT) Gs[e] = g_G[e];
    __syncthreads();
    const int k = blk * NT + tid;
    if (k >= DIN) return;
    float acc[DOUT];
    #pragma unroll
    for (int d = 0; d < DOUT; d++) acc[d] = 0.0f;
    for (int m = 0; m < U; m++) {
        const float w = Win[(size_t)k * U + m];
        #pragma unroll
        for (int d = 0; d < DOUT; d++) acc[d] += Gs[d * U + m] * w;
    }
    #pragma unroll
    for (int d = 0; d < DOUT; d++) g_F[k * DOUT + d] = acc[d];
}

// =====================================================================
// final x-pass: one row per thread, F smem-resident (stride 12)
// =====================================================================
__device__ void final_body(float* Fs, float* fsv,
                           const float* __restrict__ x, float* __restrict__ out) {
    const int tid = threadIdx.x;
    for (int e = tid; e < DIN * DOUT; e += NT) {
        const int k = e / DOUT, d = e - k * DOUT;
        Fs[k * 12 + d] = g_F[e];
    }
    if (tid < DOUT) fsv[tid] = g_f[tid];
    __syncthreads();

    const int j = (int)blockIdx.x + NCTA * tid;
    if (j >= BATCH) return;
    const float* xr = x + (size_t)j * DIN;
    float acc[DOUT];
    #pragma unroll
    for (int d = 0; d < DOUT; d++) acc[d] = fsv[d];

    for (int k = 0; k < DIN; k += 8) {
        float4 xa = *(const float4*)&xr[k];
        float4 xb = *(const float4*)&xr[k + 4];
        float xk[8] = {xa.x, xa.y, xa.z, xa.w, xb.x, xb.y, xb.z, xb.w};
        #pragma unroll
        for (int kk = 0; kk < 8; kk++) {
            const float xv = xk[kk];
            const float* Fp = &Fs[(k + kk) * 12];
            float4 f0 = *(const float4*)&Fp[0];
            float4 f1 = *(const float4*)&Fp[4];
            float2 f2 = *(const float2*)&Fp[8];
            acc[0] += xv * f0.x; acc[1] += xv * f0.y;
            acc[2] += xv * f0.z; acc[3] += xv * f0.w;
            acc[4] += xv * f1.x; acc[5] += xv * f1.y;
            acc[6] += xv * f1.z; acc[7] += xv * f1.w;
            acc[8] += xv * f2.x; acc[9] += xv * f2.y;
        }
    }
    #pragma unroll
    for (int d = 0; d < DOUT; d++) out[(size_t)j * DOUT + d] = acc[d];
}

// =====================================================================
// THE mega kernel: everything in ONE launch
// =====================================================================
__global__ __launch_bounds__(NT) void mega_kernel(const float* __restrict__ B0,
                                                  const float* __restrict__ q,
                                                  const float* __restrict__ Wout,
                                                  const float* __restrict__ bin,
                                                  const float* __restrict__ bout,
                                                  const float* __restrict__ Win,
                                                  const float* __restrict__ x,
                                                  float* __restrict__ out) {
    __shared__ __align__(16) float shbuf[9408];   // gemm tiles / folds / Fs
    __shared__ __align__(16) float sp[2][NB];
    __shared__ float sipv[NB];
    __shared__ float c0s[U], c1s[U], rq[U];
    __shared__ float fsv[16];
    const int cta = blockIdx.x;
    const int tid = threadIdx.x;

    // P0: reset inversion flags
    if (cta == 0 && tid < NL * NSTEP) ((unsigned int*)g_flagw)[tid] = 0u;
    grid_sync();

    // P1: flag-synced GENP inversion (48 CTAs)
    if (cta < 48) invert_body(B0, cta >> 3, cta & 7, sp, sipv);
    grid_sync();

    // P2: R = 2I - B0*M   (96 tiles)
    if (cta < 96) {
        const int l = cta >> 4, t = cta & 15;
        gemm_tile(shbuf, B0 + (size_t)l * SZ, g_M[l], g_R[l], nullptr, 1, t & 3, t >> 2);
    }
    grid_sync();

    // P3: M2 = M*R with fused MTn = -M2^T   (96 tiles)
    if (cta < 96) {
        const int l = cta >> 4, t = cta & 15;
        gemm_tile(shbuf, g_M[l], g_R[l], g_M2[l], g_MTn[l], 2, t & 3, t >> 2);
    }
    grid_sync();

    // P4: T_z = MTn[2z+1]*M2[2z] -> g_M[z]  (48 tiles);  CTA147: const 0-1
    if (cta < 48) {
        const int z = cta >> 4, t = cta & 15;
        gemm_tile(shbuf, g_MTn[2 * z + 1], g_M2[2 * z], g_M[z], nullptr, 0, t & 3, t >> 2);
    } else if (cta == NCTA - 1) {
        if (tid < U) { c0s[tid] = 0.0f; c1s[tid] = 0.0f; }
        const_layers(0, 2, q, c0s, c1s, rq);
    }
    grid_sync();

    // P5: TT = T1*T0 -> g_M[3]  (16 tiles);  CTA147: const 2-3
    if (cta < 16) gemm_tile(shbuf, g_M[1], g_M[0], g_M[3], nullptr, 0, cta & 3, cta >> 2);
    else if (cta == NCTA - 1) const_layers(2, 4, q, c0s, c1s, rq);
    grid_sync();

    // P6: K = T2*TT -> g_M[4]  (16 tiles);  CTA147: const 4-5 + publish
    if (cta < 16) gemm_tile(shbuf, g_M[2], g_M[3], g_M[4], nullptr, 0, cta & 3, cta >> 2);
    else if (cta == NCTA - 1) {
        const_layers(4, 6, q, c0s, c1s, rq);
        if (tid < U) g_c[tid] = c0s[tid];
    }
    grid_sync();

    // P7: foldG (CTA 0)
    if (cta == 0) foldG_body(shbuf, Wout, g_M[4], g_c, bin, bout);
    grid_sync();

    // P8: foldF (CTAs 0-1)
    if (cta < 2) foldF_body(shbuf, Win, cta);
    grid_sync();

    // P9: final x-pass (all CTAs)
    final_body(shbuf, fsv, x, out);
}

// =====================================================================
// launch  (1 launch total)
// =====================================================================
extern "C" void kernel_launch(void* const* d_in, const int* in_sizes, int n_in,
                              void* d_out, int out_size) {
    const float* x    = (const float*)d_in[0];
    const float* Win  = (const float*)d_in[1];
    const float* bin  = (const float*)d_in[2];
    const float* B0   = (const float*)d_in[3];
    const float* q    = (const float*)d_in[4];
    const float* Wout = (const float*)d_in[5];
    const float* bout = (const float*)d_in[6];
    float* out = (float*)d_out;

    mega_kernel<<<NCTA, NT>>>(B0, q, Wout, bin, bout, Win, x, out);
}